// round 8
// baseline (speedup 1.0000x reference)
#include <cuda_runtime.h>
#include <cuda_bf16.h>
#include <cstdint>

#define NB      16
#define CIN     256
#define COUT    256
#define HWSZ    1024
#define PT      128
#define NSTAGE  128          // 2 input channels per stage
#define NT      256          // 8 warps, 2(M) x 4(N), 64x64 warp tiles

// K order (56 cols): col = k*6 + term*2 + ch  (term 0:hi*hi 1:lo*hi 2:hi*lo)
#define A_STRIDE 112
#define A_SZ     (128 * A_STRIDE)    // 14336
#define B_STRIDE 528
#define B_SZ     (56 * B_STRIDE)     // 29568
#define X_SZ     8192
#define A_OFF    0
#define B_OFF    (2 * A_SZ)          // 28672
#define X_OFF    (B_OFF + 2 * B_SZ)  // 87808
#define SMEM_DYN (X_OFF + 4 * X_SZ)  // 120576  (4-deep x ring)

__device__ __align__(16) unsigned char g_wp[(size_t)NSTAGE * 56 * 512];

// ---------------- helpers ----------------
__device__ __forceinline__ uint32_t smem_u32(const void* p) {
    uint32_t a;
    asm("{ .reg .u64 t; cvta.to.shared.u64 t, %1; cvt.u32.u64 %0, t; }" : "=r"(a) : "l"(p));
    return a;
}
__device__ __forceinline__ void cp16(uint32_t d, const void* g) {
    asm volatile("cp.async.cg.shared.global [%0], [%1], 16;" :: "r"(d), "l"(g));
}
#define CP_COMMIT() asm volatile("cp.async.commit_group;" ::: "memory")
#define CP_WAIT0()  asm volatile("cp.async.wait_group 0;" ::: "memory")
#define CP_WAIT1()  asm volatile("cp.async.wait_group 1;" ::: "memory")

__device__ __forceinline__ void ldm_x4(uint32_t r[4], uint32_t a) {
    asm volatile("ldmatrix.sync.aligned.m8n8.x4.shared.b16 {%0,%1,%2,%3}, [%4];"
                 : "=r"(r[0]), "=r"(r[1]), "=r"(r[2]), "=r"(r[3]) : "r"(a));
}
__device__ __forceinline__ void ldm_x4_t(uint32_t r[4], uint32_t a) {
    asm volatile("ldmatrix.sync.aligned.m8n8.x4.trans.shared.b16 {%0,%1,%2,%3}, [%4];"
                 : "=r"(r[0]), "=r"(r[1]), "=r"(r[2]), "=r"(r[3]) : "r"(a));
}
__device__ __forceinline__ void mma16816(float d[4], const uint32_t a[4], const uint32_t b[2]) {
    asm volatile("mma.sync.aligned.m16n8k16.row.col.f32.bf16.bf16.f32 "
                 "{%0,%1,%2,%3},{%4,%5,%6,%7},{%8,%9},{%0,%1,%2,%3};"
                 : "+f"(d[0]), "+f"(d[1]), "+f"(d[2]), "+f"(d[3])
                 : "r"(a[0]), "r"(a[1]), "r"(a[2]), "r"(a[3]), "r"(b[0]), "r"(b[1]));
}
__device__ __forceinline__ void mma1688(float d[4], const uint32_t a[2], uint32_t b) {
    asm volatile("mma.sync.aligned.m16n8k8.row.col.f32.bf16.bf16.f32 "
                 "{%0,%1,%2,%3},{%4,%5},{%6},{%0,%1,%2,%3};"
                 : "+f"(d[0]), "+f"(d[1]), "+f"(d[2]), "+f"(d[3])
                 : "r"(a[0]), "r"(a[1]), "r"(b));
}

// ---------------- weight prep ----------------
__global__ void prep_weights(const float* __restrict__ weight) {
    const int j = blockIdx.x * blockDim.x + threadIdx.x;
    if (j >= NSTAGE * 56 * 64) return;
    const int o4 = j & 63;
    const int kcol = (j >> 6) % 56;
    const int s = j / (56 * 64);
    __nv_bfloat16 v[4];
    if (kcol >= 54) {
        v[0] = v[1] = v[2] = v[3] = __float2bfloat16(0.f);
    } else {
        const int k = kcol / 6, rem = kcol % 6, t = rem >> 1, ch = rem & 1;
        #pragma unroll
        for (int i = 0; i < 4; ++i) {
            const float w = weight[(size_t)(4 * o4 + i) * 2304 + (2 * s + ch) * 9 + k];
            const __nv_bfloat16 hi = __float2bfloat16(w);
            v[i] = (t == 2) ? __float2bfloat16(w - __bfloat162float(hi)) : hi;
        }
    }
    *(uint2*)(g_wp + ((size_t)s * 56 + kcol) * 512 + o4 * 8) = *(const uint2*)v;
}

// ---------------- main kernel ----------------
__global__ __launch_bounds__(NT, 1)
void dcn_mma_kernel(const float* __restrict__ x,
                    const float* __restrict__ offset,
                    float* __restrict__ out)
{
    extern __shared__ char sm[];
    const uint32_t sb = smem_u32(sm);

    const int tid  = threadIdx.x;
    const int wid  = tid >> 5, lane = tid & 31;
    const int n    = blockIdx.y;
    const int p0   = blockIdx.x * PT;
    const int warpM = wid & 1;            // 2 M-tiles of 64
    const int warpN = (wid >> 1) & 3;     // 4 N-tiles of 64

    // zero A pad cols (bytes 108..111) of both buffers
    *(uint32_t*)(sm + A_OFF + (tid >> 7) * A_SZ + (tid & 127) * A_STRIDE + 108) = 0;

    // ---- sampling tables -> registers (5 entries/thread) ----
    uint32_t tlo[5], thi[5];
    float4 twt[5];
    #pragma unroll
    for (int e = 0; e < 5; ++e) {
        const int j = tid + e * NT;
        if (j < 9 * PT) {
            const int k = j >> 7, p = j & 127;
            const int gp = p0 + p;
            const float2 d2 = *reinterpret_cast<const float2*>(
                offset + ((size_t)n * HWSZ + gp) * 18 + 2 * k);
            const float py = (float)(gp >> 5) + (float)(k / 3 - 1) + d2.x;
            const float px = (float)(gp & 31) + (float)(k % 3 - 1) + d2.y;
            const float y0 = floorf(py), x0 = floorf(px);
            const float ly = py - y0, lx = px - x0;
            const float hy = 1.f - ly, hx = 1.f - lx;
            const float vy0 = (y0 >= 0.f && y0 <= 31.f) ? 1.f : 0.f;
            const float vy1 = (y0 >= -1.f && y0 <= 30.f) ? 1.f : 0.f;
            const float vx0 = (x0 >= 0.f && x0 <= 31.f) ? 1.f : 0.f;
            const float vx1 = (x0 >= -1.f && x0 <= 30.f) ? 1.f : 0.f;
            const uint32_t iy0 = (uint32_t)(int)fminf(fmaxf(y0, 0.f), 31.f);
            const uint32_t iy1 = (uint32_t)(int)fminf(fmaxf(y0 + 1.f, 0.f), 31.f);
            const uint32_t ix0 = (uint32_t)(int)fminf(fmaxf(x0, 0.f), 31.f);
            const uint32_t ix1 = (uint32_t)(int)fminf(fmaxf(x0 + 1.f, 0.f), 31.f);
            tlo[e] = (iy0 * 32 + ix0) | ((iy0 * 32 + ix1) << 16);
            thi[e] = (iy1 * 32 + ix0) | ((iy1 * 32 + ix1) << 16);
            twt[e] = make_float4(hy * hx * vy0 * vx0, hy * lx * vy0 * vx1,
                                 ly * hx * vy1 * vx0, ly * lx * vy1 * vx1);
        } else {
            tlo[e] = thi[e] = 0;
            twt[e] = make_float4(0.f, 0.f, 0.f, 0.f);
        }
    }

    const float* xn = x + (size_t)n * CIN * HWSZ;

    // ---- async staging ----
    auto issue_b = [&](int st) {   // 1792 x 16B = 7/thread
        const char* gsrc = (const char*)g_wp + (size_t)st * (56 * 512);
        const uint32_t bdst = sb + B_OFF + (st & 1) * B_SZ;
        #pragma unroll
        for (int q = 0; q < 7; ++q) {
            const int idx = tid + q * NT;
            const int row = idx >> 5, ch = idx & 31;
            cp16(bdst + row * B_STRIDE + ch * 16, gsrc + row * 512 + ch * 16);
        }
    };
    auto issue_x = [&](int st) {   // 8KB = 2/thread
        const uint32_t xd = sb + X_OFF + (st & 3) * X_SZ;
        const char* gs = (const char*)(xn + (size_t)(2 * st) * HWSZ);
        cp16(xd + tid * 16, gs + tid * 16);
        cp16(xd + (tid + NT) * 16, gs + (tid + NT) * 16);
    };

    // ---- single build element (e-th slice of the s-th A tile) ----
    auto build_e = [&](int st, int e) {
        const int j = tid + e * NT;
        if (e == 4 && j >= 9 * PT) return;
        const float* xp0 = (const float*)(sm + X_OFF + (st & 3) * X_SZ);
        const float* xp1 = xp0 + 1024;
        char* abuf = sm + A_OFF + (st & 1) * A_SZ;
        const int k = j >> 7, p = j & 127;
        const int i00 = tlo[e] & 0xFFFF, i01 = tlo[e] >> 16;
        const int i10 = thi[e] & 0xFFFF, i11 = thi[e] >> 16;
        const float4 w = twt[e];
        const float v0 = w.x * xp0[i00] + w.y * xp0[i01] + w.z * xp0[i10] + w.w * xp0[i11];
        const float v1 = w.x * xp1[i00] + w.y * xp1[i01] + w.z * xp1[i10] + w.w * xp1[i11];
        const __nv_bfloat16 h0 = __float2bfloat16(v0);
        const __nv_bfloat16 l0 = __float2bfloat16(v0 - __bfloat162float(h0));
        const __nv_bfloat16 h1 = __float2bfloat16(v1);
        const __nv_bfloat16 l1 = __float2bfloat16(v1 - __bfloat162float(h1));
        const uint32_t hh = ((uint32_t)*(const unsigned short*)&h1 << 16)
                          |  (uint32_t)*(const unsigned short*)&h0;
        const uint32_t ll = ((uint32_t)*(const unsigned short*)&l1 << 16)
                          |  (uint32_t)*(const unsigned short*)&l0;
        char* dst = abuf + p * A_STRIDE + k * 12;
        *(uint32_t*)(dst)     = hh;
        *(uint32_t*)(dst + 4) = ll;
        *(uint32_t*)(dst + 8) = hh;
    };

    // ---- accumulators: 4 m16 x 8 n8 ----
    float acc[4][8][4];
    #pragma unroll
    for (int i = 0; i < 4; ++i)
        #pragma unroll
        for (int j = 0; j < 8; ++j)
            #pragma unroll
            for (int q = 0; q < 4; ++q) acc[i][j][q] = 0.f;

    const uint32_t aRowOff  = (uint32_t)(warpM * 64 + (lane & 15)) * A_STRIDE
                            + (uint32_t)(lane >> 4) * 16;
    const uint32_t aTailOff = (uint32_t)(warpM * 64 + lane) * A_STRIDE + 96;
    const uint32_t bRowOff  = (uint32_t)(lane & 15) * B_STRIDE
                            + (uint32_t)(warpN * 128) + (uint32_t)(lane >> 4) * 16;
    const uint32_t bTailOff = (uint32_t)(48 + (lane & 7)) * B_STRIDE
                            + (uint32_t)(warpN * 128) + (uint32_t)((lane >> 3) & 3) * 16;

    auto mma_kc = [&](uint32_t ab, uint32_t bb, int kc) {
        uint32_t a[4][4];
        #pragma unroll
        for (int mi = 0; mi < 4; ++mi)
            ldm_x4(a[mi], ab + aRowOff + mi * 16 * A_STRIDE + kc * 32);
        #pragma unroll
        for (int jt = 0; jt < 4; ++jt) {
            uint32_t b[4];
            ldm_x4_t(b, bb + bRowOff + kc * 16 * B_STRIDE + jt * 32);
            #pragma unroll
            for (int mi = 0; mi < 4; ++mi) {
                mma16816(acc[mi][2 * jt],     a[mi], b);
                mma16816(acc[mi][2 * jt + 1], a[mi], b + 2);
            }
        }
    };
    auto mma_tail = [&](uint32_t ab, uint32_t bb) {
        uint32_t at[8];
        ldm_x4(at,     ab + aTailOff);
        ldm_x4(at + 4, ab + aTailOff + 32 * A_STRIDE);
        #pragma unroll
        for (int half = 0; half < 2; ++half) {
            uint32_t b[4];
            ldm_x4_t(b, bb + bTailOff + half * 64);
            #pragma unroll
            for (int mi = 0; mi < 4; ++mi)
                #pragma unroll
                for (int q = 0; q < 4; ++q)
                    mma1688(acc[mi][half * 4 + q], at + mi * 2, b[q]);
        }
    };

    // ---- prologue: x(0..2), B(0) ----
    issue_x(0);
    issue_x(1);
    issue_x(2);
    issue_b(0);
    CP_COMMIT();
    CP_WAIT0();
    __syncthreads();
    #pragma unroll
    for (int e = 0; e < 5; ++e) build_e(0, e);
    __syncthreads();

    // ---- main loop: intra-warp interleave of build(s+1) and mma(s) ----
    #pragma unroll 1
    for (int s = 0; s < NSTAGE; ++s) {
        const bool more = (s + 1 < NSTAGE);
        if (more) issue_b(s + 1);
        CP_COMMIT();                           // group: B(s+1)
        if (s + 3 < NSTAGE) issue_x(s + 3);
        CP_COMMIT();                           // group: x(s+3)

        const uint32_t ab = sb + A_OFF + (s & 1) * A_SZ;
        const uint32_t bb = sb + B_OFF + (s & 1) * B_SZ;
        if (more) build_e(s + 1, 0);
        mma_kc(ab, bb, 0);
        if (more) build_e(s + 1, 1);
        mma_kc(ab, bb, 1);
        if (more) build_e(s + 1, 2);
        mma_kc(ab, bb, 2);
        if (more) { build_e(s + 1, 3); build_e(s + 1, 4); }
        mma_tail(ab, bb);

        CP_WAIT1();                            // B(s+1), x(s+2) landed; x(s+3) may fly
        __syncthreads();
    }

    // ---- epilogue ----
    const int pbase = p0 + warpM * 64 + (lane >> 2);
    const int obase = warpN * 64 + (lane & 3) * 2;
    float* ob = out + (size_t)n * COUT * HWSZ;
    #pragma unroll
    for (int mt = 0; mt < 4; ++mt) {
        #pragma unroll
        for (int j = 0; j < 8; ++j) {
            const int o = obase + j * 8;
            const int p = pbase + mt * 16;
            ob[(size_t)o * HWSZ + p]           = acc[mt][j][0];
            ob[(size_t)(o + 1) * HWSZ + p]     = acc[mt][j][1];
            ob[(size_t)o * HWSZ + p + 8]       = acc[mt][j][2];
            ob[(size_t)(o + 1) * HWSZ + p + 8] = acc[mt][j][3];
        }
    }
}

extern "C" void kernel_launch(void* const* d_in, const int* in_sizes, int n_in,
                              void* d_out, int out_size)
{
    const float* x      = (const float*)d_in[0];
    const float* offset = (const float*)d_in[1];
    const float* weight = (const float*)d_in[2];
    float* out          = (float*)d_out;

    static int smem_set = 0;
    if (!smem_set) {
        cudaFuncSetAttribute(dcn_mma_kernel,
                             cudaFuncAttributeMaxDynamicSharedMemorySize, SMEM_DYN);
        smem_set = 1;
    }

    prep_weights<<<(NSTAGE * 56 * 64 + 255) / 256, 256>>>(weight);
    dim3 grid(HWSZ / PT, NB);                 // 8 x 16 = 128 blocks, one wave
    dcn_mma_kernel<<<grid, NT, SMEM_DYN>>>(x, offset, out);
}

// round 9
// speedup vs baseline: 1.3566x; 1.3566x over previous
#include <cuda_runtime.h>
#include <cuda_fp16.h>
#include <cstdint>

#define NB      16
#define CIN     256
#define COUT    256
#define HWSZ    1024
#define PT      128
#define NSTAGE  128          // 2 input channels per stage
#define NT      256          // 8 warps, 2(M) x 4(N), 64x64 warp tiles

// K order (36 cols + 4 pad): col = k*4 + term*2 + ch   (term 0: vhi, 1: vlo; B has whi in both)
#define A_STRIDE 80                  // 40 fp16 cols; 20-word stride -> ldmatrix conflict-free
#define A_SZ     (128 * A_STRIDE)    // 10240
#define B_STRIDE 528                 // 256 cols + 8 pad
#define B_SZ     (40 * B_STRIDE)     // 21120
#define X_SZ     8192
#define A_OFF    0
#define B_OFF    (2 * A_SZ)          // 20480
#define X_OFF    (B_OFF + 2 * B_SZ)  // 62720
#define SMEM_DYN (X_OFF + 4 * X_SZ)  // 95488

// packed weights: [stage][40 k][256 o] fp16, rows 512B
__device__ __align__(16) unsigned char g_wp[(size_t)NSTAGE * 40 * 512];

// ---------------- helpers ----------------
__device__ __forceinline__ uint32_t smem_u32(const void* p) {
    uint32_t a;
    asm("{ .reg .u64 t; cvta.to.shared.u64 t, %1; cvt.u32.u64 %0, t; }" : "=r"(a) : "l"(p));
    return a;
}
__device__ __forceinline__ void cp16(uint32_t d, const void* g) {
    asm volatile("cp.async.cg.shared.global [%0], [%1], 16;" :: "r"(d), "l"(g));
}
#define CP_COMMIT() asm volatile("cp.async.commit_group;" ::: "memory")
#define CP_WAIT0()  asm volatile("cp.async.wait_group 0;" ::: "memory")
#define CP_WAIT1()  asm volatile("cp.async.wait_group 1;" ::: "memory")

__device__ __forceinline__ void ldm_x4(uint32_t r[4], uint32_t a) {
    asm volatile("ldmatrix.sync.aligned.m8n8.x4.shared.b16 {%0,%1,%2,%3}, [%4];"
                 : "=r"(r[0]), "=r"(r[1]), "=r"(r[2]), "=r"(r[3]) : "r"(a));
}
__device__ __forceinline__ void ldm_x4_t(uint32_t r[4], uint32_t a) {
    asm volatile("ldmatrix.sync.aligned.m8n8.x4.trans.shared.b16 {%0,%1,%2,%3}, [%4];"
                 : "=r"(r[0]), "=r"(r[1]), "=r"(r[2]), "=r"(r[3]) : "r"(a));
}
__device__ __forceinline__ void mma16816(float d[4], const uint32_t a[4], const uint32_t b[2]) {
    asm volatile("mma.sync.aligned.m16n8k16.row.col.f32.f16.f16.f32 "
                 "{%0,%1,%2,%3},{%4,%5,%6,%7},{%8,%9},{%0,%1,%2,%3};"
                 : "+f"(d[0]), "+f"(d[1]), "+f"(d[2]), "+f"(d[3])
                 : "r"(a[0]), "r"(a[1]), "r"(a[2]), "r"(a[3]), "r"(b[0]), "r"(b[1]));
}
__device__ __forceinline__ void mma1688(float d[4], const uint32_t a[2], uint32_t b) {
    asm volatile("mma.sync.aligned.m16n8k8.row.col.f32.f16.f16.f32 "
                 "{%0,%1,%2,%3},{%4,%5},{%6},{%0,%1,%2,%3};"
                 : "+f"(d[0]), "+f"(d[1]), "+f"(d[2]), "+f"(d[3])
                 : "r"(a[0]), "r"(a[1]), "r"(b));
}

// ---------------- weight prep: fp16, k-major, both term slots get whi ----------------
__global__ void prep_weights(const float* __restrict__ weight) {
    const int j = blockIdx.x * blockDim.x + threadIdx.x;   // NSTAGE*40*64
    if (j >= NSTAGE * 40 * 64) return;
    const int o4 = j & 63;
    const int kcol = (j >> 6) % 40;
    const int s = j / (40 * 64);
    __half v[4];
    if (kcol >= 36) {
        v[0] = v[1] = v[2] = v[3] = __float2half(0.f);
    } else {
        const int k = kcol >> 2, ch = kcol & 1;   // term slot (bit 1) ignored: same whi
        #pragma unroll
        for (int i = 0; i < 4; ++i)
            v[i] = __float2half(weight[(size_t)(4 * o4 + i) * 2304 + (2 * s + ch) * 9 + k]);
    }
    *(uint2*)(g_wp + ((size_t)s * 40 + kcol) * 512 + o4 * 8) = *(const uint2*)v;
}

// ---------------- main kernel ----------------
__global__ __launch_bounds__(NT, 1)
void dcn_mma_kernel(const float* __restrict__ x,
                    const float* __restrict__ offset,
                    float* __restrict__ out)
{
    extern __shared__ char sm[];
    const uint32_t sb = smem_u32(sm);

    const int tid  = threadIdx.x;
    const int wid  = tid >> 5, lane = tid & 31;
    const int n    = blockIdx.y;
    const int p0   = blockIdx.x * PT;
    const int warpM = wid & 1;            // 2 M-tiles of 64
    const int warpN = (wid >> 1) & 3;     // 4 N-tiles of 64
    const int pbit  = (wid >> 2) & 1;     // SMSP-paired warps get opposite order

    // zero A pad cols 36..39 (bytes 72..79) of both buffers
    if (tid < 256) {
        uint2 z = make_uint2(0, 0);
        *(uint2*)(sm + A_OFF + (tid >> 7) * A_SZ + (tid & 127) * A_STRIDE + 72) = z;
    }

    // ---- sampling tables -> registers (5 entries/thread) ----
    uint32_t tlo[5], thi[5];
    float4 twt[5];
    #pragma unroll
    for (int e = 0; e < 5; ++e) {
        const int j = tid + e * NT;
        if (j < 9 * PT) {
            const int k = j >> 7, p = j & 127;
            const int gp = p0 + p;
            const float2 d2 = *reinterpret_cast<const float2*>(
                offset + ((size_t)n * HWSZ + gp) * 18 + 2 * k);
            const float py = (float)(gp >> 5) + (float)(k / 3 - 1) + d2.x;
            const float px = (float)(gp & 31) + (float)(k % 3 - 1) + d2.y;
            const float y0 = floorf(py), x0 = floorf(px);
            const float ly = py - y0, lx = px - x0;
            const float hy = 1.f - ly, hx = 1.f - lx;
            const float vy0 = (y0 >= 0.f && y0 <= 31.f) ? 1.f : 0.f;
            const float vy1 = (y0 >= -1.f && y0 <= 30.f) ? 1.f : 0.f;
            const float vx0 = (x0 >= 0.f && x0 <= 31.f) ? 1.f : 0.f;
            const float vx1 = (x0 >= -1.f && x0 <= 30.f) ? 1.f : 0.f;
            const uint32_t iy0 = (uint32_t)(int)fminf(fmaxf(y0, 0.f), 31.f);
            const uint32_t iy1 = (uint32_t)(int)fminf(fmaxf(y0 + 1.f, 0.f), 31.f);
            const uint32_t ix0 = (uint32_t)(int)fminf(fmaxf(x0, 0.f), 31.f);
            const uint32_t ix1 = (uint32_t)(int)fminf(fmaxf(x0 + 1.f, 0.f), 31.f);
            tlo[e] = (iy0 * 32 + ix0) | ((iy0 * 32 + ix1) << 16);
            thi[e] = (iy1 * 32 + ix0) | ((iy1 * 32 + ix1) << 16);
            twt[e] = make_float4(hy * hx * vy0 * vx0, hy * lx * vy0 * vx1,
                                 ly * hx * vy1 * vx0, ly * lx * vy1 * vx1);
        } else {
            tlo[e] = thi[e] = 0;
            twt[e] = make_float4(0.f, 0.f, 0.f, 0.f);
        }
    }

    const float* xn = x + (size_t)n * CIN * HWSZ;

    // ---- async staging ----
    auto issue_b = [&](int st) {   // 1280 x 16B = 5/thread
        const char* gsrc = (const char*)g_wp + (size_t)st * (40 * 512);
        const uint32_t bdst = sb + B_OFF + (st & 1) * B_SZ;
        #pragma unroll
        for (int q = 0; q < 5; ++q) {
            const int idx = tid + q * NT;
            const int row = idx >> 5, ch = idx & 31;
            cp16(bdst + row * B_STRIDE + ch * 16, gsrc + row * 512 + ch * 16);
        }
    };
    auto issue_x = [&](int st) {   // 8KB = 2/thread
        const uint32_t xd = sb + X_OFF + (st & 3) * X_SZ;
        const char* gs = (const char*)(xn + (size_t)(2 * st) * HWSZ);
        cp16(xd + tid * 16, gs + tid * 16);
        cp16(xd + (tid + NT) * 16, gs + (tid + NT) * 16);
    };

    // ---- build deformed, fp16-split A tile (one STS.64 per element) ----
    auto build_a = [&](int st) {
        const float* xp0 = (const float*)(sm + X_OFF + (st & 3) * X_SZ);
        const float* xp1 = xp0 + 1024;
        char* abuf = sm + A_OFF + (st & 1) * A_SZ;
        #pragma unroll
        for (int e = 0; e < 5; ++e) {
            const int j = tid + e * NT;
            if (e == 4 && j >= 9 * PT) break;
            const int k = j >> 7, p = j & 127;
            const int i00 = tlo[e] & 0xFFFF, i01 = tlo[e] >> 16;
            const int i10 = thi[e] & 0xFFFF, i11 = thi[e] >> 16;
            const float4 w = twt[e];
            const float v0 = w.x * xp0[i00] + w.y * xp0[i01] + w.z * xp0[i10] + w.w * xp0[i11];
            const float v1 = w.x * xp1[i00] + w.y * xp1[i01] + w.z * xp1[i10] + w.w * xp1[i11];
            const __half h0 = __float2half(v0);
            const __half l0 = __float2half(v0 - __half2float(h0));
            const __half h1 = __float2half(v1);
            const __half l1 = __float2half(v1 - __half2float(h1));
            uint2 pk;
            pk.x = ((uint32_t)*(const unsigned short*)&h1 << 16)
                 |  (uint32_t)*(const unsigned short*)&h0;          // term0: vhi ch0,ch1
            pk.y = ((uint32_t)*(const unsigned short*)&l1 << 16)
                 |  (uint32_t)*(const unsigned short*)&l0;          // term1: vlo ch0,ch1
            *(uint2*)(abuf + p * A_STRIDE + k * 8) = pk;
        }
    };

    // ---- accumulators: 4 m16 x 8 n8 ----
    float acc[4][8][4];
    #pragma unroll
    for (int i = 0; i < 4; ++i)
        #pragma unroll
        for (int j = 0; j < 8; ++j)
            #pragma unroll
            for (int q = 0; q < 4; ++q) acc[i][j][q] = 0.f;

    const uint32_t aRowOff  = (uint32_t)(warpM * 64 + (lane & 15)) * A_STRIDE
                            + (uint32_t)(lane >> 4) * 16;
    const uint32_t aTailOff = (uint32_t)(warpM * 64 + lane) * A_STRIDE + 64;
    const uint32_t bRowOff  = (uint32_t)(lane & 15) * B_STRIDE
                            + (uint32_t)(warpN * 128) + (uint32_t)(lane >> 4) * 16;
    const uint32_t bTailOff = (uint32_t)(32 + (lane & 7)) * B_STRIDE
                            + (uint32_t)(warpN * 128) + (uint32_t)((lane >> 3) & 3) * 16;

    auto mma_stage = [&](int st) {
        const uint32_t ab = sb + A_OFF + (st & 1) * A_SZ;
        const uint32_t bb = sb + B_OFF + (st & 1) * B_SZ;
        #pragma unroll
        for (int kc = 0; kc < 2; ++kc) {
            uint32_t a[4][4];
            #pragma unroll
            for (int mi = 0; mi < 4; ++mi)
                ldm_x4(a[mi], ab + aRowOff + mi * 16 * A_STRIDE + kc * 32);
            #pragma unroll
            for (int jt = 0; jt < 4; ++jt) {
                uint32_t b[4];
                ldm_x4_t(b, bb + bRowOff + kc * 16 * B_STRIDE + jt * 32);
                #pragma unroll
                for (int mi = 0; mi < 4; ++mi) {
                    mma16816(acc[mi][2 * jt],     a[mi], b);
                    mma16816(acc[mi][2 * jt + 1], a[mi], b + 2);
                }
            }
        }
        // k8 tail: A cols 32..39 (bytes 64..79), B rows 32..39
        uint32_t at[8];
        ldm_x4(at,     ab + aTailOff);
        ldm_x4(at + 4, ab + aTailOff + 32 * A_STRIDE);
        #pragma unroll
        for (int half = 0; half < 2; ++half) {
            uint32_t b[4];
            ldm_x4_t(b, bb + bTailOff + half * 64);
            #pragma unroll
            for (int mi = 0; mi < 4; ++mi)
                #pragma unroll
                for (int q = 0; q < 4; ++q)
                    mma1688(acc[mi][half * 4 + q], at + mi * 2, b[q]);
        }
    };

    // ---- prologue: x(0..2), B(0) ----
    issue_x(0);
    issue_x(1);
    issue_x(2);
    issue_b(0);
    CP_COMMIT();
    CP_WAIT0();
    __syncthreads();
    build_a(0);
    __syncthreads();

    // ---- main loop: SMSP stagger + non-blocking newest prefetch ----
    #pragma unroll 1
    for (int s = 0; s < NSTAGE; ++s) {
        const bool more = (s + 1 < NSTAGE);
        if (more) issue_b(s + 1);
        CP_COMMIT();                           // group: B(s+1)
        if (s + 3 < NSTAGE) issue_x(s + 3);
        CP_COMMIT();                           // group: x(s+3)
        if (pbit) {
            if (more) build_a(s + 1);
            mma_stage(s);
        } else {
            mma_stage(s);
            if (more) build_a(s + 1);
        }
        CP_WAIT1();                            // B(s+1) + x(s+2) landed; x(s+3) may fly
        __syncthreads();
    }

    // ---- epilogue ----
    const int pbase = p0 + warpM * 64 + (lane >> 2);
    const int obase = warpN * 64 + (lane & 3) * 2;
    float* ob = out + (size_t)n * COUT * HWSZ;
    #pragma unroll
    for (int mt = 0; mt < 4; ++mt) {
        #pragma unroll
        for (int j = 0; j < 8; ++j) {
            const int o = obase + j * 8;
            const int p = pbase + mt * 16;
            ob[(size_t)o * HWSZ + p]           = acc[mt][j][0];
            ob[(size_t)(o + 1) * HWSZ + p]     = acc[mt][j][1];
            ob[(size_t)o * HWSZ + p + 8]       = acc[mt][j][2];
            ob[(size_t)(o + 1) * HWSZ + p + 8] = acc[mt][j][3];
        }
    }
}

extern "C" void kernel_launch(void* const* d_in, const int* in_sizes, int n_in,
                              void* d_out, int out_size)
{
    const float* x      = (const float*)d_in[0];
    const float* offset = (const float*)d_in[1];
    const float* weight = (const float*)d_in[2];
    float* out          = (float*)d_out;

    static int smem_set = 0;
    if (!smem_set) {
        cudaFuncSetAttribute(dcn_mma_kernel,
                             cudaFuncAttributeMaxDynamicSharedMemorySize, SMEM_DYN);
        smem_set = 1;
    }

    prep_weights<<<(NSTAGE * 40 * 64 + 255) / 256, 256>>>(weight);
    dim3 grid(HWSZ / PT, NB);                 // 8 x 16 = 128 blocks, one wave
    dcn_mma_kernel<<<grid, NT, SMEM_DYN>>>(x, offset, out);
}

// round 10
// speedup vs baseline: 1.7498x; 1.2899x over previous
#include <cuda_runtime.h>
#include <cuda_fp16.h>
#include <cstdint>

#define NB      16
#define CIN     256
#define COUT    256
#define HWSZ    1024
#define PT      128
#define NSTAGE  128          // 2 input channels per stage
#define NT      256          // 8 warps, 2(M) x 4(N), 64x64 warp tiles

// K order (18 cols + 6 pad): col = k*2 + ch   (pure fp16, no split)
#define A_STRIDE 48                  // 24 fp16 cols; 3x16B stride -> ldmatrix conflict-free
#define A_SZ     (128 * A_STRIDE)    // 6144
#define B_STRIDE 528                 // 256 cols + 8 pad
#define B_SZ     (24 * B_STRIDE)     // 12672
#define X_SZ     8192
#define A_OFF    0
#define B_OFF    (2 * A_SZ)          // 12288
#define X_OFF    (B_OFF + 2 * B_SZ)  // 37632
#define SMEM_DYN (X_OFF + 4 * X_SZ)  // 70400

// packed weights: [stage][24 k][256 o] fp16, rows 512B
__device__ __align__(16) unsigned char g_wp[(size_t)NSTAGE * 24 * 512];

// ---------------- helpers ----------------
__device__ __forceinline__ uint32_t smem_u32(const void* p) {
    uint32_t a;
    asm("{ .reg .u64 t; cvta.to.shared.u64 t, %1; cvt.u32.u64 %0, t; }" : "=r"(a) : "l"(p));
    return a;
}
__device__ __forceinline__ void cp16(uint32_t d, const void* g) {
    asm volatile("cp.async.cg.shared.global [%0], [%1], 16;" :: "r"(d), "l"(g));
}
#define CP_COMMIT() asm volatile("cp.async.commit_group;" ::: "memory")
#define CP_WAIT0()  asm volatile("cp.async.wait_group 0;" ::: "memory")
#define CP_WAIT1()  asm volatile("cp.async.wait_group 1;" ::: "memory")

__device__ __forceinline__ void ldm_x4(uint32_t r[4], uint32_t a) {
    asm volatile("ldmatrix.sync.aligned.m8n8.x4.shared.b16 {%0,%1,%2,%3}, [%4];"
                 : "=r"(r[0]), "=r"(r[1]), "=r"(r[2]), "=r"(r[3]) : "r"(a));
}
__device__ __forceinline__ void ldm_x4_t(uint32_t r[4], uint32_t a) {
    asm volatile("ldmatrix.sync.aligned.m8n8.x4.trans.shared.b16 {%0,%1,%2,%3}, [%4];"
                 : "=r"(r[0]), "=r"(r[1]), "=r"(r[2]), "=r"(r[3]) : "r"(a));
}
__device__ __forceinline__ void mma16816(float d[4], const uint32_t a[4], const uint32_t b[2]) {
    asm volatile("mma.sync.aligned.m16n8k16.row.col.f32.f16.f16.f32 "
                 "{%0,%1,%2,%3},{%4,%5,%6,%7},{%8,%9},{%0,%1,%2,%3};"
                 : "+f"(d[0]), "+f"(d[1]), "+f"(d[2]), "+f"(d[3])
                 : "r"(a[0]), "r"(a[1]), "r"(a[2]), "r"(a[3]), "r"(b[0]), "r"(b[1]));
}
__device__ __forceinline__ void mma1688(float d[4], const uint32_t a[2], uint32_t b) {
    asm volatile("mma.sync.aligned.m16n8k8.row.col.f32.f16.f16.f32 "
                 "{%0,%1,%2,%3},{%4,%5},{%6},{%0,%1,%2,%3};"
                 : "+f"(d[0]), "+f"(d[1]), "+f"(d[2]), "+f"(d[3])
                 : "r"(a[0]), "r"(a[1]), "r"(b));
}

// ---------------- weight prep: fp16, k-major ----------------
__global__ void prep_weights(const float* __restrict__ weight) {
    const int j = blockIdx.x * blockDim.x + threadIdx.x;   // NSTAGE*24*64
    if (j >= NSTAGE * 24 * 64) return;
    const int o4 = j & 63;
    const int kcol = (j >> 6) % 24;
    const int s = j / (24 * 64);
    __half v[4];
    if (kcol >= 18) {
        v[0] = v[1] = v[2] = v[3] = __float2half(0.f);
    } else {
        const int k = kcol >> 1, ch = kcol & 1;
        #pragma unroll
        for (int i = 0; i < 4; ++i)
            v[i] = __float2half(weight[(size_t)(4 * o4 + i) * 2304 + (2 * s + ch) * 9 + k]);
    }
    *(uint2*)(g_wp + ((size_t)s * 24 + kcol) * 512 + o4 * 8) = *(const uint2*)v;
}

// ---------------- main kernel ----------------
__global__ __launch_bounds__(NT, 1)
void dcn_mma_kernel(const float* __restrict__ x,
                    const float* __restrict__ offset,
                    float* __restrict__ out)
{
    extern __shared__ char sm[];
    const uint32_t sb = smem_u32(sm);

    const int tid  = threadIdx.x;
    const int wid  = tid >> 5, lane = tid & 31;
    const int n    = blockIdx.y;
    const int p0   = blockIdx.x * PT;
    const int warpM = wid & 1;            // 2 M-tiles of 64
    const int warpN = (wid >> 1) & 3;     // 4 N-tiles of 64
    const int pbit  = (wid >> 2) & 1;     // SMSP-paired warps get opposite order

    // zero A pad cols 18..23 (bytes 36..47) of both buffers
    if (tid < 256) {
        char* rp = sm + A_OFF + (tid >> 7) * A_SZ + (tid & 127) * A_STRIDE;
        *(uint32_t*)(rp + 36) = 0;
        *(uint32_t*)(rp + 40) = 0;
        *(uint32_t*)(rp + 44) = 0;
    }

    // ---- sampling tables -> registers (5 entries/thread) ----
    uint32_t tlo[5], thi[5];
    float4 twt[5];
    #pragma unroll
    for (int e = 0; e < 5; ++e) {
        const int j = tid + e * NT;
        if (j < 9 * PT) {
            const int k = j >> 7, p = j & 127;
            const int gp = p0 + p;
            const float2 d2 = *reinterpret_cast<const float2*>(
                offset + ((size_t)n * HWSZ + gp) * 18 + 2 * k);
            const float py = (float)(gp >> 5) + (float)(k / 3 - 1) + d2.x;
            const float px = (float)(gp & 31) + (float)(k % 3 - 1) + d2.y;
            const float y0 = floorf(py), x0 = floorf(px);
            const float ly = py - y0, lx = px - x0;
            const float hy = 1.f - ly, hx = 1.f - lx;
            const float vy0 = (y0 >= 0.f && y0 <= 31.f) ? 1.f : 0.f;
            const float vy1 = (y0 >= -1.f && y0 <= 30.f) ? 1.f : 0.f;
            const float vx0 = (x0 >= 0.f && x0 <= 31.f) ? 1.f : 0.f;
            const float vx1 = (x0 >= -1.f && x0 <= 30.f) ? 1.f : 0.f;
            const uint32_t iy0 = (uint32_t)(int)fminf(fmaxf(y0, 0.f), 31.f);
            const uint32_t iy1 = (uint32_t)(int)fminf(fmaxf(y0 + 1.f, 0.f), 31.f);
            const uint32_t ix0 = (uint32_t)(int)fminf(fmaxf(x0, 0.f), 31.f);
            const uint32_t ix1 = (uint32_t)(int)fminf(fmaxf(x0 + 1.f, 0.f), 31.f);
            tlo[e] = (iy0 * 32 + ix0) | ((iy0 * 32 + ix1) << 16);
            thi[e] = (iy1 * 32 + ix0) | ((iy1 * 32 + ix1) << 16);
            twt[e] = make_float4(hy * hx * vy0 * vx0, hy * lx * vy0 * vx1,
                                 ly * hx * vy1 * vx0, ly * lx * vy1 * vx1);
        } else {
            tlo[e] = thi[e] = 0;
            twt[e] = make_float4(0.f, 0.f, 0.f, 0.f);
        }
    }

    const float* xn = x + (size_t)n * CIN * HWSZ;

    // ---- async staging ----
    auto issue_b = [&](int st) {   // 768 x 16B = 3/thread
        const char* gsrc = (const char*)g_wp + (size_t)st * (24 * 512);
        const uint32_t bdst = sb + B_OFF + (st & 1) * B_SZ;
        #pragma unroll
        for (int q = 0; q < 3; ++q) {
            const int idx = tid + q * NT;
            const int row = idx >> 5, ch = idx & 31;
            cp16(bdst + row * B_STRIDE + ch * 16, gsrc + row * 512 + ch * 16);
        }
    };
    auto issue_x = [&](int st) {   // 8KB = 2/thread
        const uint32_t xd = sb + X_OFF + (st & 3) * X_SZ;
        const char* gs = (const char*)(xn + (size_t)(2 * st) * HWSZ);
        cp16(xd + tid * 16, gs + tid * 16);
        cp16(xd + (tid + NT) * 16, gs + (tid + NT) * 16);
    };

    // ---- build deformed fp16 A tile (one STS.32 per element) ----
    auto build_a = [&](int st) {
        const float* xp0 = (const float*)(sm + X_OFF + (st & 3) * X_SZ);
        const float* xp1 = xp0 + 1024;
        char* abuf = sm + A_OFF + (st & 1) * A_SZ;
        #pragma unroll
        for (int e = 0; e < 5; ++e) {
            const int j = tid + e * NT;
            if (e == 4 && j >= 9 * PT) break;
            const int k = j >> 7, p = j & 127;
            const int i00 = tlo[e] & 0xFFFF, i01 = tlo[e] >> 16;
            const int i10 = thi[e] & 0xFFFF, i11 = thi[e] >> 16;
            const float4 w = twt[e];
            const float v0 = w.x * xp0[i00] + w.y * xp0[i01] + w.z * xp0[i10] + w.w * xp0[i11];
            const float v1 = w.x * xp1[i00] + w.y * xp1[i01] + w.z * xp1[i10] + w.w * xp1[i11];
            const __half h0 = __float2half(v0);
            const __half h1 = __float2half(v1);
            const uint32_t pk = ((uint32_t)*(const unsigned short*)&h1 << 16)
                              |  (uint32_t)*(const unsigned short*)&h0;
            *(uint32_t*)(abuf + p * A_STRIDE + k * 4) = pk;
        }
    };

    // ---- accumulators: 4 m16 x 8 n8 ----
    float acc[4][8][4];
    #pragma unroll
    for (int i = 0; i < 4; ++i)
        #pragma unroll
        for (int j = 0; j < 8; ++j)
            #pragma unroll
            for (int q = 0; q < 4; ++q) acc[i][j][q] = 0.f;

    const uint32_t aRowOff  = (uint32_t)(warpM * 64 + (lane & 15)) * A_STRIDE
                            + (uint32_t)(lane >> 4) * 16;
    const uint32_t aTailOff = (uint32_t)(warpM * 64 + lane) * A_STRIDE + 32;
    const uint32_t bRowOff  = (uint32_t)(lane & 15) * B_STRIDE
                            + (uint32_t)(warpN * 128) + (uint32_t)(lane >> 4) * 16;
    const uint32_t bTailOff = (uint32_t)(16 + (lane & 7)) * B_STRIDE
                            + (uint32_t)(warpN * 128) + (uint32_t)((lane >> 3) & 3) * 16;

    auto mma_stage = [&](int st) {
        const uint32_t ab = sb + A_OFF + (st & 1) * A_SZ;
        const uint32_t bb = sb + B_OFF + (st & 1) * B_SZ;
        // k16 chunk: cols 0..15
        {
            uint32_t a[4][4];
            #pragma unroll
            for (int mi = 0; mi < 4; ++mi)
                ldm_x4(a[mi], ab + aRowOff + mi * 16 * A_STRIDE);
            #pragma unroll
            for (int jt = 0; jt < 4; ++jt) {
                uint32_t b[4];
                ldm_x4_t(b, bb + bRowOff + jt * 32);
                #pragma unroll
                for (int mi = 0; mi < 4; ++mi) {
                    mma16816(acc[mi][2 * jt],     a[mi], b);
                    mma16816(acc[mi][2 * jt + 1], a[mi], b + 2);
                }
            }
        }
        // k8 tail: A cols 16..23 (bytes 32..47), B rows 16..23
        uint32_t at[8];
        ldm_x4(at,     ab + aTailOff);
        ldm_x4(at + 4, ab + aTailOff + 32 * A_STRIDE);
        #pragma unroll
        for (int half = 0; half < 2; ++half) {
            uint32_t b[4];
            ldm_x4_t(b, bb + bTailOff + half * 64);
            #pragma unroll
            for (int mi = 0; mi < 4; ++mi)
                #pragma unroll
                for (int q = 0; q < 4; ++q)
                    mma1688(acc[mi][half * 4 + q], at + mi * 2, b[q]);
        }
    };

    // ---- prologue: x(0..2), B(0) ----
    issue_x(0);
    issue_x(1);
    issue_x(2);
    issue_b(0);
    CP_COMMIT();
    CP_WAIT0();
    __syncthreads();
    build_a(0);
    __syncthreads();

    // ---- main loop: SMSP stagger + non-blocking newest prefetch ----
    #pragma unroll 1
    for (int s = 0; s < NSTAGE; ++s) {
        const bool more = (s + 1 < NSTAGE);
        if (more) issue_b(s + 1);
        CP_COMMIT();                           // group: B(s+1)
        if (s + 3 < NSTAGE) issue_x(s + 3);
        CP_COMMIT();                           // group: x(s+3)
        if (pbit) {
            if (more) build_a(s + 1);
            mma_stage(s);
        } else {
            mma_stage(s);
            if (more) build_a(s + 1);
        }
        CP_WAIT1();                            // B(s+1) + x(s+2) landed; x(s+3) may fly
        __syncthreads();
    }

    // ---- epilogue ----
    const int pbase = p0 + warpM * 64 + (lane >> 2);
    const int obase = warpN * 64 + (lane & 3) * 2;
    float* ob = out + (size_t)n * COUT * HWSZ;
    #pragma unroll
    for (int mt = 0; mt < 4; ++mt) {
        #pragma unroll
        for (int j = 0; j < 8; ++j) {
            const int o = obase + j * 8;
            const int p = pbase + mt * 16;
            ob[(size_t)o * HWSZ + p]           = acc[mt][j][0];
            ob[(size_t)(o + 1) * HWSZ + p]     = acc[mt][j][1];
            ob[(size_t)o * HWSZ + p + 8]       = acc[mt][j][2];
            ob[(size_t)(o + 1) * HWSZ + p + 8] = acc[mt][j][3];
        }
    }
}

extern "C" void kernel_launch(void* const* d_in, const int* in_sizes, int n_in,
                              void* d_out, int out_size)
{
    const float* x      = (const float*)d_in[0];
    const float* offset = (const float*)d_in[1];
    const float* weight = (const float*)d_in[2];
    float* out          = (float*)d_out;

    static int smem_set = 0;
    if (!smem_set) {
        cudaFuncSetAttribute(dcn_mma_kernel,
                             cudaFuncAttributeMaxDynamicSharedMemorySize, SMEM_DYN);
        smem_set = 1;
    }

    prep_weights<<<(NSTAGE * 24 * 64 + 255) / 256, 256>>>(weight);
    dim3 grid(HWSZ / PT, NB);                 // 8 x 16 = 128 blocks, one wave
    dcn_mma_kernel<<<grid, NT, SMEM_DYN>>>(x, offset, out);
}

// round 11
// speedup vs baseline: 2.1956x; 1.2548x over previous
#include <cuda_runtime.h>
#include <cuda_fp16.h>
#include <cstdint>

#define NB      16
#define CIN     256
#define COUT    256
#define HWSZ    1024
#define PT      128
#define NSTAGE  64           // 4 input channels per stage
#define NT      256          // 8 warps, 2(M) x 4(N), 64x64 warp tiles

// K order (36 cols + 4 pad): col = k*4 + ch   (k=0..8, ch=0..3 within stage)
#define A_STRIDE 80                  // 40 fp16 cols; 5x16B stride -> ldmatrix conflict-free
#define A_SZ     (128 * A_STRIDE)    // 10240
#define B_STRIDE 528                 // 256 cols + 8 pad
#define B_SZ     (40 * B_STRIDE)     // 21120
#define X_SZ     16384               // 1024 pos x 4ch x 4B (interleaved float4)
#define A_OFF    0
#define B_OFF    (2 * A_SZ)          // 20480
#define X_OFF    (B_OFF + 2 * B_SZ)  // 62720
#define SMEM_DYN (X_OFF + 3 * X_SZ)  // 111872

// packed weights: [stage][40 k][256 o] fp16, rows 512B
__device__ __align__(16) unsigned char g_wp[(size_t)NSTAGE * 40 * 512];
// transposed x: [n][stage][pos][4ch] float4
__device__ __align__(16) float4 g_xt[(size_t)NB * NSTAGE * HWSZ];

// ---------------- helpers ----------------
__device__ __forceinline__ uint32_t smem_u32(const void* p) {
    uint32_t a;
    asm("{ .reg .u64 t; cvta.to.shared.u64 t, %1; cvt.u32.u64 %0, t; }" : "=r"(a) : "l"(p));
    return a;
}
__device__ __forceinline__ void cp16(uint32_t d, const void* g) {
    asm volatile("cp.async.cg.shared.global [%0], [%1], 16;" :: "r"(d), "l"(g));
}
#define CP_COMMIT() asm volatile("cp.async.commit_group;" ::: "memory")
#define CP_WAIT0()  asm volatile("cp.async.wait_group 0;" ::: "memory")
#define CP_WAIT1()  asm volatile("cp.async.wait_group 1;" ::: "memory")

__device__ __forceinline__ void ldm_x4(uint32_t r[4], uint32_t a) {
    asm volatile("ldmatrix.sync.aligned.m8n8.x4.shared.b16 {%0,%1,%2,%3}, [%4];"
                 : "=r"(r[0]), "=r"(r[1]), "=r"(r[2]), "=r"(r[3]) : "r"(a));
}
__device__ __forceinline__ void ldm_x4_t(uint32_t r[4], uint32_t a) {
    asm volatile("ldmatrix.sync.aligned.m8n8.x4.trans.shared.b16 {%0,%1,%2,%3}, [%4];"
                 : "=r"(r[0]), "=r"(r[1]), "=r"(r[2]), "=r"(r[3]) : "r"(a));
}
__device__ __forceinline__ void mma16816(float d[4], const uint32_t a[4], const uint32_t b[2]) {
    asm volatile("mma.sync.aligned.m16n8k16.row.col.f32.f16.f16.f32 "
                 "{%0,%1,%2,%3},{%4,%5,%6,%7},{%8,%9},{%0,%1,%2,%3};"
                 : "+f"(d[0]), "+f"(d[1]), "+f"(d[2]), "+f"(d[3])
                 : "r"(a[0]), "r"(a[1]), "r"(a[2]), "r"(a[3]), "r"(b[0]), "r"(b[1]));
}
__device__ __forceinline__ void mma1688(float d[4], const uint32_t a[2], uint32_t b) {
    asm volatile("mma.sync.aligned.m16n8k8.row.col.f32.f16.f16.f32 "
                 "{%0,%1,%2,%3},{%4,%5},{%6},{%0,%1,%2,%3};"
                 : "+f"(d[0]), "+f"(d[1]), "+f"(d[2]), "+f"(d[3])
                 : "r"(a[0]), "r"(a[1]), "r"(b));
}

// ---------------- x transpose: [n][c][pos] -> [n][s][pos][4ch] ----------------
__global__ void prep_x(const float* __restrict__ x) {
    __shared__ float s[4][HWSZ];
    const int n = blockIdx.x >> 6, st = blockIdx.x & 63;
    const int t = threadIdx.x;                       // 256
    const float* base = x + ((size_t)n * CIN + 4 * st) * HWSZ;
    #pragma unroll
    for (int ch = 0; ch < 4; ++ch)
        ((float4*)s[ch])[t] = ((const float4*)(base + ch * HWSZ))[t];
    __syncthreads();
    float4* outp = g_xt + (size_t)(n * NSTAGE + st) * HWSZ;
    #pragma unroll
    for (int q = 0; q < 4; ++q) {
        const int p = t + q * 256;
        outp[p] = make_float4(s[0][p], s[1][p], s[2][p], s[3][p]);
    }
}

// ---------------- weight prep: fp16, k-major ----------------
__global__ void prep_weights(const float* __restrict__ weight) {
    const int j = blockIdx.x * blockDim.x + threadIdx.x;   // NSTAGE*40*64
    if (j >= NSTAGE * 40 * 64) return;
    const int o4 = j & 63;
    const int kcol = (j >> 6) % 40;
    const int s = j / (40 * 64);
    __half v[4];
    if (kcol >= 36) {
        v[0] = v[1] = v[2] = v[3] = __float2half(0.f);
    } else {
        const int k = kcol >> 2, ch = kcol & 3;
        #pragma unroll
        for (int i = 0; i < 4; ++i)
            v[i] = __float2half(weight[(size_t)(4 * o4 + i) * 2304 + (4 * s + ch) * 9 + k]);
    }
    *(uint2*)(g_wp + ((size_t)s * 40 + kcol) * 512 + o4 * 8) = *(const uint2*)v;
}

// ---------------- main kernel ----------------
__global__ __launch_bounds__(NT, 1)
void dcn_mma_kernel(const float* __restrict__ x,
                    const float* __restrict__ offset,
                    float* __restrict__ out)
{
    extern __shared__ char sm[];
    const uint32_t sb = smem_u32(sm);

    const int tid  = threadIdx.x;
    const int wid  = tid >> 5, lane = tid & 31;
    const int n    = blockIdx.y;
    const int p0   = blockIdx.x * PT;
    const int warpM = wid & 1;            // 2 M-tiles of 64
    const int warpN = (wid >> 1) & 3;     // 4 N-tiles of 64
    const int pbit  = (wid >> 2) & 1;     // SMSP-paired warps get opposite order

    // zero A pad cols 36..39 (bytes 72..79) of both buffers
    if (tid < 256) {
        uint2 z = make_uint2(0, 0);
        *(uint2*)(sm + A_OFF + (tid >> 7) * A_SZ + (tid & 127) * A_STRIDE + 72) = z;
    }

    // ---- sampling tables -> registers (5 entries/thread) ----
    uint32_t tlo[5], thi[5];
    float4 twt[5];
    #pragma unroll
    for (int e = 0; e < 5; ++e) {
        const int j = tid + e * NT;
        if (j < 9 * PT) {
            const int k = j >> 7, p = j & 127;
            const int gp = p0 + p;
            const float2 d2 = *reinterpret_cast<const float2*>(
                offset + ((size_t)n * HWSZ + gp) * 18 + 2 * k);
            const float py = (float)(gp >> 5) + (float)(k / 3 - 1) + d2.x;
            const float px = (float)(gp & 31) + (float)(k % 3 - 1) + d2.y;
            const float y0 = floorf(py), x0 = floorf(px);
            const float ly = py - y0, lx = px - x0;
            const float hy = 1.f - ly, hx = 1.f - lx;
            const float vy0 = (y0 >= 0.f && y0 <= 31.f) ? 1.f : 0.f;
            const float vy1 = (y0 >= -1.f && y0 <= 30.f) ? 1.f : 0.f;
            const float vx0 = (x0 >= 0.f && x0 <= 31.f) ? 1.f : 0.f;
            const float vx1 = (x0 >= -1.f && x0 <= 30.f) ? 1.f : 0.f;
            const uint32_t iy0 = (uint32_t)(int)fminf(fmaxf(y0, 0.f), 31.f);
            const uint32_t iy1 = (uint32_t)(int)fminf(fmaxf(y0 + 1.f, 0.f), 31.f);
            const uint32_t ix0 = (uint32_t)(int)fminf(fmaxf(x0, 0.f), 31.f);
            const uint32_t ix1 = (uint32_t)(int)fminf(fmaxf(x0 + 1.f, 0.f), 31.f);
            tlo[e] = (iy0 * 32 + ix0) | ((iy0 * 32 + ix1) << 16);
            thi[e] = (iy1 * 32 + ix0) | ((iy1 * 32 + ix1) << 16);
            twt[e] = make_float4(hy * hx * vy0 * vx0, hy * lx * vy0 * vx1,
                                 ly * hx * vy1 * vx0, ly * lx * vy1 * vx1);
        } else {
            tlo[e] = thi[e] = 0;
            twt[e] = make_float4(0.f, 0.f, 0.f, 0.f);
        }
    }

    // ---- async staging ----
    auto issue_b = [&](int st) {   // 1280 x 16B = 5/thread
        const char* gsrc = (const char*)g_wp + (size_t)st * (40 * 512);
        const uint32_t bdst = sb + B_OFF + (st & 1) * B_SZ;
        #pragma unroll
        for (int q = 0; q < 5; ++q) {
            const int idx = tid + q * NT;
            const int row = idx >> 5, ch = idx & 31;
            cp16(bdst + row * B_STRIDE + ch * 16, gsrc + row * 512 + ch * 16);
        }
    };
    auto issue_x = [&](int st) {   // 16KB = 4/thread
        const uint32_t xd = sb + X_OFF + (st % 3) * X_SZ;
        const char* gs = (const char*)(g_xt + (size_t)(n * NSTAGE + st) * HWSZ);
        #pragma unroll
        for (int q = 0; q < 4; ++q)
            cp16(xd + (tid + q * NT) * 16, gs + (tid + q * NT) * 16);
    };

    // ---- build deformed fp16 A tile: 4 LDS.128 + 1 STS.64 per element ----
    auto build_a = [&](int st) {
        const float4* xp = (const float4*)(sm + X_OFF + (st % 3) * X_SZ);
        char* abuf = sm + A_OFF + (st & 1) * A_SZ;
        #pragma unroll
        for (int e = 0; e < 5; ++e) {
            const int j = tid + e * NT;
            if (e == 4 && j >= 9 * PT) break;
            const int k = j >> 7, p = j & 127;
            const float4 c00 = xp[tlo[e] & 0xFFFF];
            const float4 c01 = xp[tlo[e] >> 16];
            const float4 c10 = xp[thi[e] & 0xFFFF];
            const float4 c11 = xp[thi[e] >> 16];
            const float4 w = twt[e];
            const float v0 = w.x * c00.x + w.y * c01.x + w.z * c10.x + w.w * c11.x;
            const float v1 = w.x * c00.y + w.y * c01.y + w.z * c10.y + w.w * c11.y;
            const float v2 = w.x * c00.z + w.y * c01.z + w.z * c10.z + w.w * c11.z;
            const float v3 = w.x * c00.w + w.y * c01.w + w.z * c10.w + w.w * c11.w;
            const __half2 h01 = __floats2half2_rn(v0, v1);
            const __half2 h23 = __floats2half2_rn(v2, v3);
            uint2 pk;
            pk.x = *(const uint32_t*)&h01;
            pk.y = *(const uint32_t*)&h23;
            *(uint2*)(abuf + p * A_STRIDE + k * 8) = pk;
        }
    };

    // ---- accumulators: 4 m16 x 8 n8 ----
    float acc[4][8][4];
    #pragma unroll
    for (int i = 0; i < 4; ++i)
        #pragma unroll
        for (int j = 0; j < 8; ++j)
            #pragma unroll
            for (int q = 0; q < 4; ++q) acc[i][j][q] = 0.f;

    const uint32_t aRowOff  = (uint32_t)(warpM * 64 + (lane & 15)) * A_STRIDE
                            + (uint32_t)(lane >> 4) * 16;
    const uint32_t aTailOff = (uint32_t)(warpM * 64 + lane) * A_STRIDE + 64;
    const uint32_t bRowOff  = (uint32_t)(lane & 15) * B_STRIDE
                            + (uint32_t)(warpN * 128) + (uint32_t)(lane >> 4) * 16;
    const uint32_t bTailOff = (uint32_t)(32 + (lane & 7)) * B_STRIDE
                            + (uint32_t)(warpN * 128) + (uint32_t)((lane >> 3) & 3) * 16;

    auto mma_stage = [&](int st) {
        const uint32_t ab = sb + A_OFF + (st & 1) * A_SZ;
        const uint32_t bb = sb + B_OFF + (st & 1) * B_SZ;
        #pragma unroll
        for (int kc = 0; kc < 2; ++kc) {
            uint32_t a[4][4];
            #pragma unroll
            for (int mi = 0; mi < 4; ++mi)
                ldm_x4(a[mi], ab + aRowOff + mi * 16 * A_STRIDE + kc * 32);
            #pragma unroll
            for (int jt = 0; jt < 4; ++jt) {
                uint32_t b[4];
                ldm_x4_t(b, bb + bRowOff + kc * 16 * B_STRIDE + jt * 32);
                #pragma unroll
                for (int mi = 0; mi < 4; ++mi) {
                    mma16816(acc[mi][2 * jt],     a[mi], b);
                    mma16816(acc[mi][2 * jt + 1], a[mi], b + 2);
                }
            }
        }
        // k8 tail: A cols 32..39 (bytes 64..79), B rows 32..39
        uint32_t at[8];
        ldm_x4(at,     ab + aTailOff);
        ldm_x4(at + 4, ab + aTailOff + 32 * A_STRIDE);
        #pragma unroll
        for (int half = 0; half < 2; ++half) {
            uint32_t b[4];
            ldm_x4_t(b, bb + bTailOff + half * 64);
            #pragma unroll
            for (int mi = 0; mi < 4; ++mi)
                #pragma unroll
                for (int q = 0; q < 4; ++q)
                    mma1688(acc[mi][half * 4 + q], at + mi * 2, b[q]);
        }
    };

    // ---- prologue: x(0), x(1), B(0) ----
    issue_x(0);
    issue_x(1);
    issue_b(0);
    CP_COMMIT();
    CP_WAIT0();
    __syncthreads();
    build_a(0);
    __syncthreads();

    // ---- main loop ----
    #pragma unroll 1
    for (int s = 0; s < NSTAGE; ++s) {
        const bool more = (s + 1 < NSTAGE);
        if (more) issue_b(s + 1);
        CP_COMMIT();                           // group: B(s+1)
        if (s + 2 < NSTAGE) issue_x(s + 2);
        CP_COMMIT();                           // group: x(s+2)
        if (pbit) {
            if (more) build_a(s + 1);
            mma_stage(s);
        } else {
            mma_stage(s);
            if (more) build_a(s + 1);
        }
        CP_WAIT1();                            // B(s+1) + x(s+1) landed; x(s+2) may fly
        __syncthreads();
    }

    // ---- epilogue ----
    const int pbase = p0 + warpM * 64 + (lane >> 2);
    const int obase = warpN * 64 + (lane & 3) * 2;
    float* ob = out + (size_t)n * COUT * HWSZ;
    #pragma unroll
    for (int mt = 0; mt < 4; ++mt) {
        #pragma unroll
        for (int j = 0; j < 8; ++j) {
            const int o = obase + j * 8;
            const int p = pbase + mt * 16;
            ob[(size_t)o * HWSZ + p]           = acc[mt][j][0];
            ob[(size_t)(o + 1) * HWSZ + p]     = acc[mt][j][1];
            ob[(size_t)o * HWSZ + p + 8]       = acc[mt][j][2];
            ob[(size_t)(o + 1) * HWSZ + p + 8] = acc[mt][j][3];
        }
    }
}

extern "C" void kernel_launch(void* const* d_in, const int* in_sizes, int n_in,
                              void* d_out, int out_size)
{
    const float* x      = (const float*)d_in[0];
    const float* offset = (const float*)d_in[1];
    const float* weight = (const float*)d_in[2];
    float* out          = (float*)d_out;

    static int smem_set = 0;
    if (!smem_set) {
        cudaFuncSetAttribute(dcn_mma_kernel,
                             cudaFuncAttributeMaxDynamicSharedMemorySize, SMEM_DYN);
        smem_set = 1;
    }

    prep_x<<<NB * NSTAGE, 256>>>(x);
    prep_weights<<<(NSTAGE * 40 * 64 + 255) / 256, 256>>>(weight);
    dim3 grid(HWSZ / PT, NB);                 // 8 x 16 = 128 blocks, one wave
    dcn_mma_kernel<<<grid, NT, SMEM_DYN>>>(x, offset, out);
}

// round 12
// speedup vs baseline: 2.5773x; 1.1738x over previous
#include <cuda_runtime.h>
#include <cuda_fp16.h>
#include <cstdint>

#define NB      16
#define CIN     256
#define COUT    256
#define HWSZ    1024
#define PT      128
#define NSTAGE  32           // 8 input channels per stage
#define NT      256          // 8 warps, 2(M) x 4(N), 64x64 warp tiles

// K order (72 cols + 8 pad): col = k*8 + ch   (k=0..8, ch=0..7); 80 cols = 5 x k16 exactly
#define A_STRIDE 176                 // 88 cols; 11x16B stride -> ldmatrix conflict-free
#define A_SZ     (128 * A_STRIDE)    // 22528
#define B_STRIDE 528                 // 256 cols + 8 pad
#define B_SZ     (80 * B_STRIDE)     // 42240
#define X_SZ     16384               // 1024 pos x 8ch x 2B (fp16 interleaved)
#define A_OFF    0
#define B_OFF    (2 * A_SZ)          // 45056
#define X_OFF    (B_OFF + 2 * B_SZ)  // 129536
#define SMEM_DYN (X_OFF + 3 * X_SZ)  // 178688

// packed weights: [stage][80 k][256 o] fp16, rows 512B (rows 72..79 zero)
__device__ __align__(16) unsigned char g_wp[(size_t)NSTAGE * 80 * 512];
// transposed fp16 x: [n][stage][pos][8ch] = uint4 per pos
__device__ __align__(16) uint4 g_xt[(size_t)NB * NSTAGE * HWSZ];

// ---------------- helpers ----------------
__device__ __forceinline__ uint32_t smem_u32(const void* p) {
    uint32_t a;
    asm("{ .reg .u64 t; cvta.to.shared.u64 t, %1; cvt.u32.u64 %0, t; }" : "=r"(a) : "l"(p));
    return a;
}
__device__ __forceinline__ void cp16(uint32_t d, const void* g) {
    asm volatile("cp.async.cg.shared.global [%0], [%1], 16;" :: "r"(d), "l"(g));
}
#define CP_COMMIT() asm volatile("cp.async.commit_group;" ::: "memory")
#define CP_WAIT0()  asm volatile("cp.async.wait_group 0;" ::: "memory")
#define CP_WAIT1()  asm volatile("cp.async.wait_group 1;" ::: "memory")
#define CP_WAIT2()  asm volatile("cp.async.wait_group 2;" ::: "memory")

__device__ __forceinline__ void ldm_x4(uint32_t r[4], uint32_t a) {
    asm volatile("ldmatrix.sync.aligned.m8n8.x4.shared.b16 {%0,%1,%2,%3}, [%4];"
                 : "=r"(r[0]), "=r"(r[1]), "=r"(r[2]), "=r"(r[3]) : "r"(a));
}
__device__ __forceinline__ void ldm_x4_t(uint32_t r[4], uint32_t a) {
    asm volatile("ldmatrix.sync.aligned.m8n8.x4.trans.shared.b16 {%0,%1,%2,%3}, [%4];"
                 : "=r"(r[0]), "=r"(r[1]), "=r"(r[2]), "=r"(r[3]) : "r"(a));
}
__device__ __forceinline__ void mma16816(float d[4], const uint32_t a[4], const uint32_t b[2]) {
    asm volatile("mma.sync.aligned.m16n8k16.row.col.f32.f16.f16.f32 "
                 "{%0,%1,%2,%3},{%4,%5,%6,%7},{%8,%9},{%0,%1,%2,%3};"
                 : "+f"(d[0]), "+f"(d[1]), "+f"(d[2]), "+f"(d[3])
                 : "r"(a[0]), "r"(a[1]), "r"(a[2]), "r"(a[3]), "r"(b[0]), "r"(b[1]));
}

// ---------------- x transpose+cast: [n][c][pos] fp32 -> [n][s][pos][8ch] fp16 ----------------
__global__ void prep_x(const float* __restrict__ x) {
    __shared__ float s[8][HWSZ];
    const int n = blockIdx.x >> 5, st = blockIdx.x & 31;
    const int t = threadIdx.x;                       // 256
    const float* base = x + ((size_t)n * CIN + 8 * st) * HWSZ;
    #pragma unroll
    for (int ch = 0; ch < 8; ++ch)
        ((float4*)s[ch])[t] = ((const float4*)(base + ch * HWSZ))[t];
    __syncthreads();
    uint4* outp = g_xt + (size_t)(n * NSTAGE + st) * HWSZ;
    #pragma unroll
    for (int q = 0; q < 4; ++q) {
        const int p = t + q * 256;
        const __half2 h01 = __floats2half2_rn(s[0][p], s[1][p]);
        const __half2 h23 = __floats2half2_rn(s[2][p], s[3][p]);
        const __half2 h45 = __floats2half2_rn(s[4][p], s[5][p]);
        const __half2 h67 = __floats2half2_rn(s[6][p], s[7][p]);
        uint4 v;
        v.x = *(const uint32_t*)&h01;
        v.y = *(const uint32_t*)&h23;
        v.z = *(const uint32_t*)&h45;
        v.w = *(const uint32_t*)&h67;
        outp[p] = v;
    }
}

// ---------------- weight prep: fp16, k-major ----------------
__global__ void prep_weights(const float* __restrict__ weight) {
    const int j = blockIdx.x * blockDim.x + threadIdx.x;   // NSTAGE*80*64
    if (j >= NSTAGE * 80 * 64) return;
    const int o4 = j & 63;
    const int kcol = (j >> 6) % 80;
    const int s = j / (80 * 64);
    __half v[4];
    if (kcol >= 72) {
        v[0] = v[1] = v[2] = v[3] = __float2half(0.f);
    } else {
        const int k = kcol >> 3, ch = kcol & 7;
        #pragma unroll
        for (int i = 0; i < 4; ++i)
            v[i] = __float2half(weight[(size_t)(4 * o4 + i) * 2304 + (8 * s + ch) * 9 + k]);
    }
    *(uint2*)(g_wp + ((size_t)s * 80 + kcol) * 512 + o4 * 8) = *(const uint2*)v;
}

// ---------------- main kernel ----------------
__global__ __launch_bounds__(NT, 1)
void dcn_mma_kernel(const float* __restrict__ x,
                    const float* __restrict__ offset,
                    float* __restrict__ out)
{
    extern __shared__ char sm[];
    const uint32_t sb = smem_u32(sm);

    const int tid  = threadIdx.x;
    const int wid  = tid >> 5, lane = tid & 31;
    const int n    = blockIdx.y;
    const int p0   = blockIdx.x * PT;
    const int warpM = wid & 1;            // 2 M-tiles of 64
    const int warpN = (wid >> 1) & 3;     // 4 N-tiles of 64
    const int pbit  = (wid >> 2) & 1;     // SMSP-paired warps get opposite order

    // zero A pad cols 72..79 (bytes 144..159) of both buffers
    if (tid < 256) {
        uint4 z = make_uint4(0, 0, 0, 0);
        *(uint4*)(sm + A_OFF + (tid >> 7) * A_SZ + (tid & 127) * A_STRIDE + 144) = z;
    }

    // ---- sampling tables -> registers (5 entries/thread) ----
    uint32_t tlo[5], thi[5];
    float4 twt[5];
    #pragma unroll
    for (int e = 0; e < 5; ++e) {
        const int j = tid + e * NT;
        if (j < 9 * PT) {
            const int k = j >> 7, p = j & 127;
            const int gp = p0 + p;
            const float2 d2 = *reinterpret_cast<const float2*>(
                offset + ((size_t)n * HWSZ + gp) * 18 + 2 * k);
            const float py = (float)(gp >> 5) + (float)(k / 3 - 1) + d2.x;
            const float px = (float)(gp & 31) + (float)(k % 3 - 1) + d2.y;
            const float y0 = floorf(py), x0 = floorf(px);
            const float ly = py - y0, lx = px - x0;
            const float hy = 1.f - ly, hx = 1.f - lx;
            const float vy0 = (y0 >= 0.f && y0 <= 31.f) ? 1.f : 0.f;
            const float vy1 = (y0 >= -1.f && y0 <= 30.f) ? 1.f : 0.f;
            const float vx0 = (x0 >= 0.f && x0 <= 31.f) ? 1.f : 0.f;
            const float vx1 = (x0 >= -1.f && x0 <= 30.f) ? 1.f : 0.f;
            const uint32_t iy0 = (uint32_t)(int)fminf(fmaxf(y0, 0.f), 31.f);
            const uint32_t iy1 = (uint32_t)(int)fminf(fmaxf(y0 + 1.f, 0.f), 31.f);
            const uint32_t ix0 = (uint32_t)(int)fminf(fmaxf(x0, 0.f), 31.f);
            const uint32_t ix1 = (uint32_t)(int)fminf(fmaxf(x0 + 1.f, 0.f), 31.f);
            tlo[e] = (iy0 * 32 + ix0) | ((iy0 * 32 + ix1) << 16);
            thi[e] = (iy1 * 32 + ix0) | ((iy1 * 32 + ix1) << 16);
            twt[e] = make_float4(hy * hx * vy0 * vx0, hy * lx * vy0 * vx1,
                                 ly * hx * vy1 * vx0, ly * lx * vy1 * vx1);
        } else {
            tlo[e] = thi[e] = 0;
            twt[e] = make_float4(0.f, 0.f, 0.f, 0.f);
        }
    }

    // ---- async staging ----
    auto issue_b = [&](int st) {   // 2560 x 16B = 10/thread
        const char* gsrc = (const char*)g_wp + (size_t)st * (80 * 512);
        const uint32_t bdst = sb + B_OFF + (st & 1) * B_SZ;
        #pragma unroll
        for (int q = 0; q < 10; ++q) {
            const int idx = tid + q * NT;
            const int row = idx >> 5, ch = idx & 31;
            cp16(bdst + row * B_STRIDE + ch * 16, gsrc + row * 512 + ch * 16);
        }
    };
    auto issue_x = [&](int st) {   // 16KB = 4/thread
        const uint32_t xd = sb + X_OFF + (st % 3) * X_SZ;
        const char* gs = (const char*)(g_xt + (size_t)(n * NSTAGE + st) * HWSZ);
        #pragma unroll
        for (int q = 0; q < 4; ++q)
            cp16(xd + (tid + q * NT) * 16, gs + (tid + q * NT) * 16);
    };

    // ---- build deformed fp16 A tile: 4 LDS.128 (8ch each) + 1 STS.128 per element ----
    auto build_a = [&](int st) {
        const uint4* xp = (const uint4*)(sm + X_OFF + (st % 3) * X_SZ);
        char* abuf = sm + A_OFF + (st & 1) * A_SZ;
        #pragma unroll
        for (int e = 0; e < 5; ++e) {
            const int j = tid + e * NT;
            if (e == 4 && j >= 9 * PT) break;
            const int k = j >> 7, p = j & 127;
            uint4 c00 = xp[tlo[e] & 0xFFFF];
            uint4 c01 = xp[tlo[e] >> 16];
            uint4 c10 = xp[thi[e] & 0xFFFF];
            uint4 c11 = xp[thi[e] >> 16];
            const float4 w = twt[e];
            uint4 r;
            const uint32_t* p00 = &c00.x;
            const uint32_t* p01 = &c01.x;
            const uint32_t* p10 = &c10.x;
            const uint32_t* p11 = &c11.x;
            uint32_t* pr = &r.x;
            #pragma unroll
            for (int q = 0; q < 4; ++q) {
                const float2 f00 = __half22float2(*(const __half2*)&p00[q]);
                const float2 f01 = __half22float2(*(const __half2*)&p01[q]);
                const float2 f10 = __half22float2(*(const __half2*)&p10[q]);
                const float2 f11 = __half22float2(*(const __half2*)&p11[q]);
                const float va = w.x * f00.x + w.y * f01.x + w.z * f10.x + w.w * f11.x;
                const float vb = w.x * f00.y + w.y * f01.y + w.z * f10.y + w.w * f11.y;
                const __half2 h = __floats2half2_rn(va, vb);
                pr[q] = *(const uint32_t*)&h;
            }
            *(uint4*)(abuf + p * A_STRIDE + k * 16) = r;
        }
    };

    // ---- accumulators: 4 m16 x 8 n8 ----
    float acc[4][8][4];
    #pragma unroll
    for (int i = 0; i < 4; ++i)
        #pragma unroll
        for (int j = 0; j < 8; ++j)
            #pragma unroll
            for (int q = 0; q < 4; ++q) acc[i][j][q] = 0.f;

    const uint32_t aRowOff = (uint32_t)(warpM * 64 + (lane & 15)) * A_STRIDE
                           + (uint32_t)(lane >> 4) * 16;
    const uint32_t bRowOff = (uint32_t)(lane & 15) * B_STRIDE
                           + (uint32_t)(warpN * 128) + (uint32_t)(lane >> 4) * 16;

    auto mma_stage = [&](int st) {
        const uint32_t ab = sb + A_OFF + (st & 1) * A_SZ;
        const uint32_t bb = sb + B_OFF + (st & 1) * B_SZ;
        #pragma unroll
        for (int kc = 0; kc < 5; ++kc) {
            uint32_t a[4][4];
            #pragma unroll
            for (int mi = 0; mi < 4; ++mi)
                ldm_x4(a[mi], ab + aRowOff + mi * 16 * A_STRIDE + kc * 32);
            #pragma unroll
            for (int jt = 0; jt < 4; ++jt) {
                uint32_t b[4];
                ldm_x4_t(b, bb + bRowOff + kc * 16 * B_STRIDE + jt * 32);
                #pragma unroll
                for (int mi = 0; mi < 4; ++mi) {
                    mma16816(acc[mi][2 * jt],     a[mi], b);
                    mma16816(acc[mi][2 * jt + 1], a[mi], b + 2);
                }
            }
        }
    };

    // ---- prologue: x(0), x(1), B(0) in one group ----
    issue_x(0);
    issue_x(1);
    issue_b(0);
    CP_COMMIT();
    CP_WAIT0();
    __syncthreads();
    build_a(0);
    __syncthreads();

    // ---- main loop ----
    #pragma unroll 1
    for (int s = 0; s < NSTAGE; ++s) {
        const bool more = (s + 1 < NSTAGE);
        if (more) issue_b(s + 1);
        CP_COMMIT();                           // group: B(s+1)
        if (s + 2 < NSTAGE) issue_x(s + 2);
        CP_COMMIT();                           // group: x(s+2)
        CP_WAIT2();                            // x(s+1) guaranteed landed before build
        if (pbit) {
            if (more) build_a(s + 1);
            mma_stage(s);
        } else {
            mma_stage(s);
            if (more) build_a(s + 1);
        }
        CP_WAIT1();                            // B(s+1) landed; x(s+2) may fly
        __syncthreads();
    }

    // ---- epilogue ----
    const int pbase = p0 + warpM * 64 + (lane >> 2);
    const int obase = warpN * 64 + (lane & 3) * 2;
    float* ob = out + (size_t)n * COUT * HWSZ;
    #pragma unroll
    for (int mt = 0; mt < 4; ++mt) {
        #pragma unroll
        for (int j = 0; j < 8; ++j) {
            const int o = obase + j * 8;
            const int p = pbase + mt * 16;
            ob[(size_t)o * HWSZ + p]           = acc[mt][j][0];
            ob[(size_t)(o + 1) * HWSZ + p]     = acc[mt][j][1];
            ob[(size_t)o * HWSZ + p + 8]       = acc[mt][j][2];
            ob[(size_t)(o + 1) * HWSZ + p + 8] = acc[mt][j][3];
        }
    }
}

extern "C" void kernel_launch(void* const* d_in, const int* in_sizes, int n_in,
                              void* d_out, int out_size)
{
    const float* x      = (const float*)d_in[0];
    const float* offset = (const float*)d_in[1];
    const float* weight = (const float*)d_in[2];
    float* out          = (float*)d_out;

    static int smem_set = 0;
    if (!smem_set) {
        cudaFuncSetAttribute(dcn_mma_kernel,
                             cudaFuncAttributeMaxDynamicSharedMemorySize, SMEM_DYN);
        smem_set = 1;
    }

    prep_x<<<NB * NSTAGE, 256>>>(x);
    prep_weights<<<(NSTAGE * 80 * 64 + 255) / 256, 256>>>(weight);
    dim3 grid(HWSZ / PT, NB);                 // 8 x 16 = 128 blocks, one wave
    dcn_mma_kernel<<<grid, NT, SMEM_DYN>>>(x, offset, out);
}